// round 3
// baseline (speedup 1.0000x reference)
#include <cuda_runtime.h>
#include <math.h>

#define NB   128
#define H    128
#define NPG  8
#define BT   3
#define AA   243
#define PAIRS 192
#define TPB  512
#define ABST 132

typedef unsigned long long u64;

__device__ __forceinline__ u64 pack2(float lo, float hi) {
    u64 r; asm("mov.b64 %0, {%1, %2};" : "=l"(r) : "f"(lo), "f"(hi)); return r;
}
__device__ __forceinline__ void fma2(u64& d, u64 a, u64 b) {
    asm("fma.rn.f32x2 %0, %1, %2, %0;" : "+l"(d) : "l"(a), "l"(b));
}
__device__ __forceinline__ float2 unpack2(u64 v) {
    float2 f; asm("mov.b64 {%0, %1}, %2;" : "=f"(f.x), "=f"(f.y) : "l"(v)); return f;
}

__global__ __launch_bounds__(TPB, 1)
void fused_apm_kernel(const float* __restrict__ nf,      // (1024,128)
                      const float* __restrict__ mask,    // (128,243)
                      const float* __restrict__ Wfcv1,   // (128,64)
                      const float* __restrict__ bfcv1,   // (64)
                      const float* __restrict__ Wfcv2,   // (64,1)
                      const float* __restrict__ bfcv2,   // (1)
                      const float* __restrict__ Wa2,     // (256,128)
                      const float* __restrict__ ba2,     // (128)
                      const float* __restrict__ Wfin,    // (128,3)
                      const float* __restrict__ bfin,    // (3)
                      const int*   __restrict__ idxmask, // (128,243)
                      float* __restrict__ out)           // probs[128*243] ++ readout[128]
{
    const int b = blockIdx.x;
    const int t = threadIdx.x;

    __shared__ __align__(16) u64   ps8[4][H];        // packed relu'd node pairs (n2, c)
    __shared__ __align__(16) float Pt[2][2][NPG][H]; // GEMM partials [chalf][grp][n][h]
    __shared__ __align__(16) float ABf[2][NPG][ABST];
    __shared__ __align__(16) float ssum[H];
    __shared__ __align__(16) float sba[H];
    __shared__ __align__(16) float sWfT[BT][H];
    __shared__ float sc[PAIRS];
    __shared__ float red[8];
    __shared__ float wred[16];
    __shared__ float bc[2];

    // ---- EARLY prefetch of softmax-tail inputs (cold DRAM, consumed last) ----
    int   im = 0; float mk = 0.f;
    if (t < AA) {
        im = idxmask[b * AA + t];
        mk = mask[b * AA + t];
    }

    // ---- stage node features (relu'd, node-pair packed) + small weights ----
    for (int idx = t; idx < NPG * H; idx += TPB) {
        int n = idx >> 7, c = idx & 127;
        float v = fmaxf(nf[(b * NPG + n) * H + c], 0.f);
        reinterpret_cast<float*>(&ps8[n >> 1][c])[n & 1] = v;
    }
    if (t < H) {
        float a = 0.f;
        #pragma unroll
        for (int n = 0; n < NPG; n++) a += nf[(b * NPG + n) * H + t];
        ssum[t] = a;
        sba[t]  = ba2[t];
    } else if (t < H + H * BT) {
        int idx = t - H;
        int h = idx & 127, k = idx >> 7;
        sWfT[k][h] = Wfin[h * BT + k];
    }
    __syncthreads();

    // ---- Ai/Bj GEMM, c-split + f32x2: thread = (chalf, grp, h) ----
    {
        const int h   = t & 127;
        const int grp = (t >> 7) & 1;
        const int ch  = t >> 8;
        const float* W = Wa2 + grp * H * H + ch * 64 * H + h;
        u64 acc0 = 0, acc1 = 0, acc2 = 0, acc3 = 0;
        const ulonglong2* p0 = reinterpret_cast<const ulonglong2*>(&ps8[0][ch * 64]);
        const ulonglong2* p1 = reinterpret_cast<const ulonglong2*>(&ps8[1][ch * 64]);
        const ulonglong2* p2 = reinterpret_cast<const ulonglong2*>(&ps8[2][ch * 64]);
        const ulonglong2* p3 = reinterpret_cast<const ulonglong2*>(&ps8[3][ch * 64]);
        #pragma unroll 8
        for (int cc = 0; cc < 64; cc += 2) {
            float w0 = W[cc * H];
            float w1 = W[cc * H + H];
            u64 wp0 = pack2(w0, w0);
            u64 wp1 = pack2(w1, w1);
            ulonglong2 q;
            q = p0[cc >> 1]; fma2(acc0, q.x, wp0); fma2(acc0, q.y, wp1);
            q = p1[cc >> 1]; fma2(acc1, q.x, wp0); fma2(acc1, q.y, wp1);
            q = p2[cc >> 1]; fma2(acc2, q.x, wp0); fma2(acc2, q.y, wp1);
            q = p3[cc >> 1]; fma2(acc3, q.x, wp0); fma2(acc3, q.y, wp1);
        }
        float2 f;
        f = unpack2(acc0); Pt[ch][grp][0][h] = f.x; Pt[ch][grp][1][h] = f.y;
        f = unpack2(acc1); Pt[ch][grp][2][h] = f.x; Pt[ch][grp][3][h] = f.y;
        f = unpack2(acc2); Pt[ch][grp][4][h] = f.x; Pt[ch][grp][5][h] = f.y;
        f = unpack2(acc3); Pt[ch][grp][6][h] = f.x; Pt[ch][grp][7][h] = f.y;
    }
    __syncthreads();

    // ---- reduce c-halves into padded final AB ----
    {
        const int idx = t * 4;
        const int grp = idx >> 10, n = (idx >> 7) & 7, h = idx & 127;
        const float* P0 = &Pt[0][0][0][0];
        float4 a = *reinterpret_cast<const float4*>(P0 + idx);
        float4 c = *reinterpret_cast<const float4*>(P0 + 2048 + idx);
        float4 r;
        r.x = a.x + c.x; r.y = a.y + c.y; r.z = a.z + c.z; r.w = a.w + c.w;
        *reinterpret_cast<float4*>(&ABf[grp][n][h]) = r;
    }
    __syncthreads();

    // ---- pair scores (threads 0-191) + readout MLP (threads 192-255) ----
    if (t < PAIRS) {
        const int k = t >> 6;
        const int p = t & 63;
        const int i = p >> 3, j = p & 7;
        const float4* A4 = reinterpret_cast<const float4*>(ABf[0][i]);
        const float4* B4 = reinterpret_cast<const float4*>(ABf[1][j]);
        const float4* W4 = reinterpret_cast<const float4*>(sWfT[k]);
        const float4* Z4 = reinterpret_cast<const float4*>(sba);
        float acc = bfin[k];
        #pragma unroll 8
        for (int hq = 0; hq < H / 4; hq++) {
            float4 a = A4[hq], bb = B4[hq], w = W4[hq], z = Z4[hq];
            acc += fmaxf(a.x + bb.x + z.x, 0.f) * w.x
                 + fmaxf(a.y + bb.y + z.y, 0.f) * w.y
                 + fmaxf(a.z + bb.z + z.z, 0.f) * w.z
                 + fmaxf(a.w + bb.w + z.w, 0.f) * w.w;
        }
        sc[p * BT + k] = acc;
    } else if (t < 256) {
        const int j = t - PAIRS;
        float acc = bfcv1[j];
        const float4* S4 = reinterpret_cast<const float4*>(ssum);
        #pragma unroll 8
        for (int c4 = 0; c4 < H / 4; c4++) {
            float4 sv = S4[c4];
            const int c = c4 * 4;
            acc += sv.x * Wfcv1[(c + 0) * 64 + j]
                 + sv.y * Wfcv1[(c + 1) * 64 + j]
                 + sv.z * Wfcv1[(c + 2) * 64 + j]
                 + sv.w * Wfcv1[(c + 3) * 64 + j];
        }
        float hid = fmaxf(acc, 0.f) * Wfcv2[j];
        #pragma unroll
        for (int off = 16; off > 0; off >>= 1)
            hid += __shfl_down_sync(0xffffffffu, hid, off);
        if ((t & 31) == 0) red[t >> 5] = hid;   // red[6], red[7]
    }
    __syncthreads();

    if (t == 0) out[NB * AA + b] = red[6] + red[7] + bfcv2[0];

    // ---- gather + softmax over 243 (im/mk already in registers) ----
    float fv = 0.f, val = -INFINITY;
    if (t < AA) {
        fv = ((im < PAIRS) ? sc[im] : 0.f) + mk;
        val = fv;
    }
    float m = val;
    #pragma unroll
    for (int off = 16; off > 0; off >>= 1)
        m = fmaxf(m, __shfl_xor_sync(0xffffffffu, m, off));
    if ((t & 31) == 0) wred[t >> 5] = m;
    __syncthreads();
    if (t == 0) {
        float mm = wred[0];
        #pragma unroll
        for (int w = 1; w < 16; w++) mm = fmaxf(mm, wred[w]);
        bc[0] = mm;
    }
    __syncthreads();
    float e = (t < AA) ? __expf(fv - bc[0]) : 0.f;
    float sr = e;
    #pragma unroll
    for (int off = 16; off > 0; off >>= 1)
        sr += __shfl_xor_sync(0xffffffffu, sr, off);
    if ((t & 31) == 0) wred[t >> 5] = sr;
    __syncthreads();
    if (t == 0) {
        float sm = 0.f;
        #pragma unroll
        for (int w = 0; w < 16; w++) sm += wred[w];
        bc[1] = sm;
    }
    __syncthreads();
    if (t < AA) out[b * AA + t] = e / bc[1];
}

extern "C" void kernel_launch(void* const* d_in, const int* in_sizes, int n_in,
                              void* d_out, int out_size) {
    const float* nf     = (const float*)d_in[0];
    const float* mask   = (const float*)d_in[2];
    const float* Wfcv1  = (const float*)d_in[3];
    const float* bfcv1  = (const float*)d_in[4];
    const float* Wfcv2  = (const float*)d_in[5];
    const float* bfcv2  = (const float*)d_in[6];
    const float* Wa2    = (const float*)d_in[7];
    const float* ba2    = (const float*)d_in[8];
    const float* Wfin   = (const float*)d_in[9];
    const float* bfin   = (const float*)d_in[10];
    const int*   idxm   = (const int*)d_in[11];
    float* out = (float*)d_out;

    fused_apm_kernel<<<NB, TPB>>>(nf, mask, Wfcv1, bfcv1, Wfcv2, bfcv2,
                                  Wa2, ba2, Wfin, bfin, idxm, out);
}